// round 14
// baseline (speedup 1.0000x reference)
#include <cuda_runtime.h>
#include <cuda_bf16.h>
#include <math.h>

// ============================================================================
// DMAModel: 2-layer weighted GAT + link scoring (sparse formulation).
// GEMMs: bf16x3 tensor cores (pre-split hi/lo), cp.async + ldmatrix.
// Attention: fused, 256-thread blocks, 3-barrier hybrid softmax, split-k gather.
// All chain kernels launched with programmatic dependent launch (PDL).
// ============================================================================

#define N_NODES 4096
#define D_IN    256
#define D_HID   512
#define D_OUT   256
#define CAP     512

typedef unsigned short ushort_t;

// ---------------- scratch (device globals) ----------------------------------
__device__ float    g_h1 [N_NODES * D_HID];
__device__ float    g_h2 [N_NODES * D_OUT];
__device__ float    g_o2 [N_NODES * D_OUT];
__device__ float    g_hb [N_NODES * D_OUT];
__device__ float    g_src[N_NODES];
__device__ float    g_dst[N_NODES];
__device__ int      g_cols[(size_t)N_NODES * CAP];
__device__ float    g_wv  [(size_t)N_NODES * CAP];
__device__ int      g_cnt [N_NODES];
// bf16 hi/lo split operands
__device__ ushort_t g_xh [N_NODES * D_IN],  g_xl [N_NODES * D_IN];
__device__ ushort_t g_w1h[D_IN * D_HID],    g_w1l[D_IN * D_HID];
__device__ ushort_t g_w2h[D_HID * D_OUT],   g_w2l[D_HID * D_OUT];
__device__ ushort_t g_wbh[D_OUT * D_OUT],   g_wbl[D_OUT * D_OUT];
__device__ ushort_t g_o1h[N_NODES * D_HID], g_o1l[N_NODES * D_HID];
__device__ ushort_t g_o2h[N_NODES * D_OUT], g_o2l[N_NODES * D_OUT];

// ---------------- bf16 helpers ------------------------------------------------
__device__ __forceinline__ unsigned cvt2_bf16(float e0, float e1) {
    unsigned r;
    asm("cvt.rn.bf16x2.f32 %0, %1, %2;" : "=r"(r) : "f"(e1), "f"(e0));
    return r;
}
__device__ __forceinline__ void split2(float e0, float e1, unsigned& h, unsigned& l) {
    h = cvt2_bf16(e0, e1);
    const float h0 = __uint_as_float(h << 16);
    const float h1 = __uint_as_float(h & 0xffff0000u);
    l = cvt2_bf16(e0 - h0, e1 - h1);
}
__device__ __forceinline__ void ldm_x4(unsigned& r0, unsigned& r1,
                                       unsigned& r2, unsigned& r3, unsigned addr) {
    asm volatile("ldmatrix.sync.aligned.m8n8.x4.shared.b16 {%0,%1,%2,%3}, [%4];"
                 : "=r"(r0), "=r"(r1), "=r"(r2), "=r"(r3) : "r"(addr));
}
__device__ __forceinline__ void ldm_x4_t(unsigned& r0, unsigned& r1,
                                         unsigned& r2, unsigned& r3, unsigned addr) {
    asm volatile("ldmatrix.sync.aligned.m8n8.x4.trans.shared.b16 {%0,%1,%2,%3}, [%4];"
                 : "=r"(r0), "=r"(r1), "=r"(r2), "=r"(r3) : "r"(addr));
}
__device__ __forceinline__ void mma_bf16(float& c0, float& c1, float& c2, float& c3,
                                         unsigned a0, unsigned a1, unsigned a2, unsigned a3,
                                         unsigned b0, unsigned b1) {
    asm volatile(
        "mma.sync.aligned.m16n8k16.row.col.f32.bf16.bf16.f32 "
        "{%0,%1,%2,%3}, {%4,%5,%6,%7}, {%8,%9}, {%0,%1,%2,%3};"
        : "+f"(c0), "+f"(c1), "+f"(c2), "+f"(c3)
        : "r"(a0), "r"(a1), "r"(a2), "r"(a3), "r"(b0), "r"(b1));
}
__device__ __forceinline__ void cp16(void* d, const void* s) {
    unsigned da = (unsigned)__cvta_generic_to_shared(d);
    asm volatile("cp.async.ca.shared.global [%0], [%1], 16;" :: "r"(da), "l"(s));
}
__device__ __forceinline__ void cp_commit() { asm volatile("cp.async.commit_group;"); }
__device__ __forceinline__ void cp_wait1()  { asm volatile("cp.async.wait_group 1;"); }
__device__ __forceinline__ void cp_wait0()  { asm volatile("cp.async.wait_group 0;"); }

// ---------------- startup split: x, W1, W2, Wb -> bf16 hi/lo ------------------
#define XF4  (N_NODES * D_IN  / 4)
#define W1F4 (D_IN    * D_HID / 4)
#define W2F4 (D_HID   * D_OUT / 4)
#define WBF4 (D_OUT   * D_OUT / 4)
#define SPLIT_BLOCKS ((XF4 + W1F4 + W2F4 + WBF4) / 256)    // 1344

__global__ __launch_bounds__(256) void split_inputs_k(const float* __restrict__ x,
                                                      const float* __restrict__ W1,
                                                      const float* __restrict__ W2,
                                                      const float* __restrict__ Wb)
{
    const int idx = blockIdx.x * 256 + threadIdx.x;
    const float* src; ushort_t *dh, *dl; int l;
    if (idx < XF4)                     { src = x;  dh = g_xh;  dl = g_xl;  l = idx; }
    else if (idx < XF4 + W1F4)         { src = W1; dh = g_w1h; dl = g_w1l; l = idx - XF4; }
    else if (idx < XF4 + W1F4 + W2F4)  { src = W2; dh = g_w2h; dl = g_w2l; l = idx - XF4 - W1F4; }
    else                               { src = Wb; dh = g_wbh; dl = g_wbl; l = idx - XF4 - W1F4 - W2F4; }
    const float4 v = ((const float4*)src)[l];
    unsigned h0, l0, h1, l1;
    split2(v.x, v.y, h0, l0);
    split2(v.z, v.w, h1, l1);
    ((uint2*)dh)[l] = make_uint2(h0, h1);
    ((uint2*)dl)[l] = make_uint2(l0, l1);
    cudaTriggerProgrammaticLaunchCompletion();
}

// ---------------- bf16x3 tensor-core GEMM ------------------------------------
#define GBM 64
#define GBN 64
#define GBK 32
#define AS  40
#define BS  72

struct __align__(16) SmemBuf {
    ushort_t Ah[GBM][AS];
    ushort_t Al[GBM][AS];
    ushort_t Bh[GBK][BS];
    ushort_t Bl[GBK][BS];
};

__device__ __forceinline__ void gemm_issue(SmemBuf* sb,
                                           const ushort_t* __restrict__ Ahg,
                                           const ushort_t* __restrict__ Alg,
                                           const ushort_t* __restrict__ Bhg,
                                           const ushort_t* __restrict__ Blg,
                                           int N, int K, int bm, int bn, int c, int tid)
{
    const int aRow = tid >> 2, aSeg = (tid & 3) * 8;
    const size_t aOff = (size_t)(bm + aRow) * K + c * GBK + aSeg;
    cp16(&sb->Ah[aRow][aSeg], Ahg + aOff);
    cp16(&sb->Al[aRow][aSeg], Alg + aOff);
    const int bRow = tid >> 3, bSeg = (tid & 7) * 8;
    const size_t bOff = (size_t)(c * GBK + bRow) * N + bn + bSeg;
    cp16(&sb->Bh[bRow][bSeg], Bhg + bOff);
    cp16(&sb->Bl[bRow][bSeg], Blg + bOff);
    cp_commit();
}

__device__ __forceinline__ void bf16_gemm_body(const ushort_t* __restrict__ Ahg,
                                               const ushort_t* __restrict__ Alg,
                                               const ushort_t* __restrict__ Bhg,
                                               const ushort_t* __restrict__ Blg,
                                               float* __restrict__ C,
                                               int N, int K, int bm, int bn,
                                               SmemBuf* sb)
{
    const int tid  = threadIdx.x;
    const int lane = tid & 31;
    const int wid  = tid >> 5;
    const int g    = lane >> 2;
    const int tig  = lane & 3;
    const int m_off = (wid & 3) * 16;
    const int n_off = (wid >> 2) * 32;

    unsigned ah_p[2], al_p[2], bh_p[2], bl_p[2];
    #pragma unroll
    for (int b = 0; b < 2; b++) {
        ah_p[b] = (unsigned)__cvta_generic_to_shared(
            &sb[b].Ah[m_off + (lane & 15)][(lane >> 4) * 8]);
        al_p[b] = (unsigned)__cvta_generic_to_shared(
            &sb[b].Al[m_off + (lane & 15)][(lane >> 4) * 8]);
        bh_p[b] = (unsigned)__cvta_generic_to_shared(
            &sb[b].Bh[lane & 15][(lane >> 4) * 8]);
        bl_p[b] = (unsigned)__cvta_generic_to_shared(
            &sb[b].Bl[lane & 15][(lane >> 4) * 8]);
    }

    float acc[4][4];
    #pragma unroll
    for (int nt = 0; nt < 4; nt++)
        #pragma unroll
        for (int r = 0; r < 4; r++) acc[nt][r] = 0.0f;

    const int nchunks = K / GBK;
    gemm_issue(&sb[0], Ahg, Alg, Bhg, Blg, N, K, bm, bn, 0, tid);

    for (int c = 0; c < nchunks; c++) {
        if (c + 1 < nchunks) {
            gemm_issue(&sb[(c + 1) & 1], Ahg, Alg, Bhg, Blg, N, K, bm, bn, c + 1, tid);
            cp_wait1();
        } else {
            cp_wait0();
        }
        __syncthreads();

        const int b = c & 1;
        #pragma unroll
        for (int kc = 0; kc < 2; kc++) {
            unsigned ah0, ah1, ah2, ah3, al0, al1, al2, al3;
            ldm_x4(ah0, ah1, ah2, ah3, ah_p[b] + kc * 32);
            ldm_x4(al0, al1, al2, al3, al_p[b] + kc * 32);
            unsigned bh[8], bl[8];
            const unsigned brow_off = kc * (16 * BS * 2);
            ldm_x4_t(bh[0], bh[1], bh[2], bh[3], bh_p[b] + brow_off + n_off * 2);
            ldm_x4_t(bh[4], bh[5], bh[6], bh[7], bh_p[b] + brow_off + (n_off + 16) * 2);
            ldm_x4_t(bl[0], bl[1], bl[2], bl[3], bl_p[b] + brow_off + n_off * 2);
            ldm_x4_t(bl[4], bl[5], bl[6], bl[7], bl_p[b] + brow_off + (n_off + 16) * 2);

            #pragma unroll
            for (int nt = 0; nt < 4; nt++) {
                mma_bf16(acc[nt][0], acc[nt][1], acc[nt][2], acc[nt][3],
                         ah0, ah1, ah2, ah3, bh[2 * nt], bh[2 * nt + 1]);
                mma_bf16(acc[nt][0], acc[nt][1], acc[nt][2], acc[nt][3],
                         ah0, ah1, ah2, ah3, bl[2 * nt], bl[2 * nt + 1]);
                mma_bf16(acc[nt][0], acc[nt][1], acc[nt][2], acc[nt][3],
                         al0, al1, al2, al3, bh[2 * nt], bh[2 * nt + 1]);
            }
        }
        __syncthreads();
    }

    const int row0 = bm + m_off + g;
    #pragma unroll
    for (int nt = 0; nt < 4; nt++) {
        const int col = bn + n_off + nt * 8 + 2 * tig;
        *(float2*)(C + (size_t)row0 * N + col)       = make_float2(acc[nt][0], acc[nt][1]);
        *(float2*)(C + (size_t)(row0 + 8) * N + col) = make_float2(acc[nt][2], acc[nt][3]);
    }
}

// ---------------- sparse build body ------------------------------------------
__device__ __forceinline__ void build_row(const float* __restrict__ adj,
                                          const float* __restrict__ amount,
                                          const float* __restrict__ count,
                                          int i)
{
    const int tid  = threadIdx.x;
    const int lane = tid & 31, warp = tid >> 5;
    __shared__ int s_wsum[8];
    __shared__ int s_total;

    const float4* arow4 = (const float4*)(adj + (size_t)i * N_NODES);
    float4 v[4];
    #pragma unroll
    for (int t = 0; t < 4; t++) v[t] = arow4[tid * 4 + t];

    unsigned m16 = 0;
    #pragma unroll
    for (int t = 0; t < 4; t++) {
        if (v[t].x > 0.0f) m16 |= 1u << (t * 4 + 0);
        if (v[t].y > 0.0f) m16 |= 1u << (t * 4 + 1);
        if (v[t].z > 0.0f) m16 |= 1u << (t * 4 + 2);
        if (v[t].w > 0.0f) m16 |= 1u << (t * 4 + 3);
    }
    const int c = __popc(m16);

    int x = c;
    #pragma unroll
    for (int o = 1; o < 32; o <<= 1) {
        int y = __shfl_up_sync(0xffffffffu, x, o);
        if (lane >= o) x += y;
    }
    if (lane == 31) s_wsum[warp] = x;
    __syncthreads();
    if (tid == 0) {
        int acc = 0;
        #pragma unroll
        for (int w = 0; w < 8; w++) { int t = s_wsum[w]; s_wsum[w] = acc; acc += t; }
        s_total = acc;
    }
    __syncthreads();

    int pos = s_wsum[warp] + x - c;
    unsigned mm = m16;
    while (mm) {
        const int b = __ffs(mm) - 1;
        mm &= mm - 1;
        const int j = tid * 16 + b;
        if (pos < CAP) {
            g_cols[(size_t)i * CAP + pos] = j;
            g_wv  [(size_t)i * CAP + pos] =
                0.5f * (amount[(size_t)i * N_NODES + j] +
                        count [(size_t)i * N_NODES + j]);
        }
        pos++;
    }
    if (tid == 0) g_cnt[i] = min(s_total, CAP);
}

// ---------------- fat kernel: layer-1 GEMM overlapped with sparse build ------
#define SG1_BLOCKS ((D_HID / GBN) * (N_NODES / GBM))   // 512
__global__ __launch_bounds__(256) void fat_build_sgemm1_k(
    float* __restrict__ h1,
    const float* __restrict__ adj, const float* __restrict__ amount,
    const float* __restrict__ count)
{
    cudaGridDependencySynchronize();
    if (blockIdx.x < SG1_BLOCKS) {
        __shared__ SmemBuf sb[2];
        const int bn = (blockIdx.x & 7) * GBN;
        const int bm = (blockIdx.x >> 3) * GBM;
        bf16_gemm_body(g_xh, g_xl, g_w1h, g_w1l, h1, D_HID, D_IN, bm, bn, sb);
    } else {
        build_row(adj, amount, count, blockIdx.x - SG1_BLOCKS);
    }
    cudaTriggerProgrammaticLaunchCompletion();
}

__global__ __launch_bounds__(256) void gemm2_k(float* __restrict__ h2)
{
    cudaGridDependencySynchronize();
    __shared__ SmemBuf sb[2];
    bf16_gemm_body(g_o1h, g_o1l, g_w2h, g_w2l, h2, D_OUT, D_HID,
                   blockIdx.y * GBM, blockIdx.x * GBN, sb);
    cudaTriggerProgrammaticLaunchCompletion();
}
__global__ __launch_bounds__(256) void gemm3_k(float* __restrict__ hb)
{
    cudaGridDependencySynchronize();
    __shared__ SmemBuf sb[2];
    bf16_gemm_body(g_o2h, g_o2l, g_wbh, g_wbl, hb, D_OUT, D_OUT,
                   blockIdx.y * GBM, blockIdx.x * GBN, sb);
    cudaTriggerProgrammaticLaunchCompletion();
}

// ---------------- rowdots: warp-per-row, MLP=4, shuffle-only reduction -------
template<int D>
__global__ __launch_bounds__(256) void rowdots_t(const float* __restrict__ h,
                                                 const float* __restrict__ asrc,
                                                 const float* __restrict__ adst)
{
    cudaGridDependencySynchronize();
    constexpr int NF4 = D / 4;
    constexpr int PERLANE = NF4 / 32;
    const int warp = threadIdx.x >> 5;
    const int lane = threadIdx.x & 31;
    const int i = blockIdx.x * 8 + warp;

    const float4* hr = (const float4*)(h + (size_t)i * D);
    const float4* a4 = (const float4*)asrc;
    const float4* b4 = (const float4*)adst;

    float4 hv[PERLANE];
    #pragma unroll
    for (int t = 0; t < PERLANE; t++) hv[t] = hr[lane + t * 32];

    float s1 = 0.0f, s2 = 0.0f;
    #pragma unroll
    for (int t = 0; t < PERLANE; t++) {
        const float4 v = hv[t];
        const float4 a = a4[lane + t * 32];
        const float4 b = b4[lane + t * 32];
        s1 += v.x * a.x + v.y * a.y + v.z * a.z + v.w * a.w;
        s2 += v.x * b.x + v.y * b.y + v.z * b.z + v.w * b.w;
    }
    #pragma unroll
    for (int o = 16; o > 0; o >>= 1) {
        s1 += __shfl_down_sync(0xffffffffu, s1, o);
        s2 += __shfl_down_sync(0xffffffffu, s2, o);
    }
    if (lane == 0) { g_src[i] = s1; g_dst[i] = s2; }
    cudaTriggerProgrammaticLaunchCompletion();
}

// ---------------- fused sparse attention softmax + SpMM + ELU ----------------
// 256 threads/block. All 8 warps run the preamble (2 strided iterations);
// hybrid shuffle+smem reductions (3 block barriers). Gather: split-k over
// NGR groups per row, smem combine, unroll 8.
template<int D>
__global__ __launch_bounds__(256) void attn_spmm_t(const float* __restrict__ h)
{
    cudaGridDependencySynchronize();
    constexpr int TPB = 256;
    constexpr int NF4 = D / 4;            // 128 (D=512) or 64 (D=256)
    constexpr int NGR = TPB / NF4;        // 2 or 4
    const int i = blockIdx.x;
    const int tid = threadIdx.x;
    const int lane = tid & 31;
    const int warp = tid >> 5;
    const int cnt = g_cnt[i];

    __shared__ float s_p  [CAP];
    __shared__ int   s_off[CAP];
    __shared__ float red  [16];

    // ---- pass 1: e + row max ----
    const float si = g_src[i];
    float lmax = -3.4e38f;
    for (int k = tid; k < cnt; k += TPB) {
        const int c = g_cols[(size_t)i * CAP + k];
        s_off[k] = c * D;
        float e = si + g_dst[c];
        e = (e >= 0.0f) ? e : 0.2f * e;
        s_p[k] = e;
        lmax = fmaxf(lmax, e);
    }
    #pragma unroll
    for (int o = 16; o > 0; o >>= 1)
        lmax = fmaxf(lmax, __shfl_xor_sync(0xffffffffu, lmax, o));
    if (lane == 0) red[warp] = lmax;
    __syncthreads();
    const float m = fmaxf(fmaxf(fmaxf(red[0], red[1]), fmaxf(red[2], red[3])),
                          fmaxf(fmaxf(red[4], red[5]), fmaxf(red[6], red[7])));

    // ---- pass 2: exp + row sum ----
    float lsum = 0.0f;
    for (int k = tid; k < cnt; k += TPB) {
        const float ex = __expf(s_p[k] - m);
        s_p[k] = ex;
        lsum += ex;
    }
    #pragma unroll
    for (int o = 16; o > 0; o >>= 1)
        lsum += __shfl_xor_sync(0xffffffffu, lsum, o);
    if (lane == 0) red[8 + warp] = lsum;
    __syncthreads();
    const float inv = (cnt > 0)
        ? (1.0f / (((red[8] + red[9]) + (red[10] + red[11])) +
                   ((red[12] + red[13]) + (red[14] + red[15])))) : 0.0f;

    // ---- pass 3: scale by inv * wv ----
    for (int k = tid; k < cnt; k += TPB)
        s_p[k] = s_p[k] * inv * g_wv[(size_t)i * CAP + k];
    __syncthreads();

    // ---- gather + ELU: NGR k-groups per row ----
    const int g  = tid / NF4;             // 0..NGR-1
    const int d4 = tid % NF4;
    float4 acc = make_float4(0.f, 0.f, 0.f, 0.f);
    #pragma unroll 8
    for (int k = g; k < cnt; k += NGR) {
        const float4 v = *(const float4*)(h + s_off[k] + (d4 << 2));
        const float p = s_p[k];
        acc.x += p * v.x; acc.y += p * v.y;
        acc.z += p * v.z; acc.w += p * v.w;
    }
    {
        __shared__ float4 s_acc[(NGR - 1) * NF4 > 0 ? (NGR - 1) * NF4 : 1];
        if (g > 0) s_acc[(g - 1) * NF4 + d4] = acc;
        __syncthreads();
        if (g == 0) {
            #pragma unroll
            for (int t = 0; t < NGR - 1; t++) {
                const float4 o = s_acc[t * NF4 + d4];
                acc.x += o.x; acc.y += o.y; acc.z += o.z; acc.w += o.w;
            }
        }
    }
    if (g == 0) {
        float4 r;
        r.x = (acc.x > 0.0f) ? acc.x : expm1f(acc.x);
        r.y = (acc.y > 0.0f) ? acc.y : expm1f(acc.y);
        r.z = (acc.z > 0.0f) ? acc.z : expm1f(acc.z);
        r.w = (acc.w > 0.0f) ? acc.w : expm1f(acc.w);
        const size_t off = (size_t)i * D + (d4 << 2);
        if (D == 256) *(float4*)(g_o2 + off) = r;
        unsigned h0, l0, h1, l1;
        split2(r.x, r.y, h0, l0);
        split2(r.z, r.w, h1, l1);
        ushort_t* oh = (D == 512) ? g_o1h : g_o2h;
        ushort_t* ol = (D == 512) ? g_o1l : g_o2l;
        *(uint2*)(oh + off) = make_uint2(h0, h1);
        *(uint2*)(ol + off) = make_uint2(l0, l1);
    }
    cudaTriggerProgrammaticLaunchCompletion();
}

// ---------------- pair scoring: sigmoid(H[i].h[j] + bb) ----------------------
__global__ __launch_bounds__(256) void pairs_k(const int* __restrict__ pairs,
                                               const float* __restrict__ bb,
                                               float* __restrict__ out, int P)
{
    cudaGridDependencySynchronize();
    const int wid  = (blockIdx.x * blockDim.x + threadIdx.x) >> 5;
    const int lane = threadIdx.x & 31;
    if (wid >= P) return;
    const int i = pairs[2 * wid + 0];
    const int j = pairs[2 * wid + 1];
    const float4* ra = (const float4*)(g_hb + (size_t)i * D_OUT);
    const float4* rb = (const float4*)(g_o2 + (size_t)j * D_OUT);
    float s = 0.0f;
    #pragma unroll
    for (int t = lane; t < D_OUT / 4; t += 32) {
        const float4 a = ra[t], b = rb[t];
        s += a.x * b.x + a.y * b.y + a.z * b.z + a.w * b.w;
    }
    #pragma unroll
    for (int o = 16; o > 0; o >>= 1) s += __shfl_down_sync(0xffffffffu, s, o);
    if (lane == 0) out[wid] = 1.0f / (1.0f + expf(-(s + bb[0])));
}

// ---------------- PDL launch helper ------------------------------------------
static inline void launch_pdl(const void* fn, dim3 grid, dim3 block, void** args)
{
    cudaLaunchConfig_t cfg = {};
    cfg.gridDim = grid;
    cfg.blockDim = block;
    cfg.dynamicSmemBytes = 0;
    cudaLaunchAttribute attr[1];
    attr[0].id = cudaLaunchAttributeProgrammaticStreamSerialization;
    attr[0].val.programmaticStreamSerializationAllowed = 1;
    cfg.attrs = attr;
    cfg.numAttrs = 1;
    cudaLaunchKernelExC(&cfg, fn, args);
}

// ============================================================================
extern "C" void kernel_launch(void* const* d_in, const int* in_sizes, int n_in,
                              void* d_out, int out_size)
{
    const float* x      = (const float*)d_in[0];
    const float* adj    = (const float*)d_in[1];
    const float* amount = (const float*)d_in[2];
    const float* count  = (const float*)d_in[3];
    const int*   pairs  = (const int*)  d_in[4];
    const float* W1     = (const float*)d_in[5];
    const float* a1s    = (const float*)d_in[6];
    const float* a1d    = (const float*)d_in[7];
    const float* W2     = (const float*)d_in[8];
    const float* a2s    = (const float*)d_in[9];
    const float* a2d    = (const float*)d_in[10];
    const float* Wb     = (const float*)d_in[11];
    const float* bb     = (const float*)d_in[12];
    float* out = (float*)d_out;
    const int P = in_sizes[4] / 2;

    float *h1, *h2, *hb;
    cudaGetSymbolAddress((void**)&h1, g_h1);
    cudaGetSymbolAddress((void**)&h2, g_h2);
    cudaGetSymbolAddress((void**)&hb, g_hb);

    // split inputs to bf16 hi/lo once (plain launch; first in chain)
    split_inputs_k<<<SPLIT_BLOCKS, 256>>>(x, W1, W2, Wb);

    // layer 1: GEMM (bf16x3) overlapped with sparse structure build
    {
        void* args[] = {&h1, (void*)&adj, (void*)&amount, (void*)&count};
        launch_pdl((const void*)fat_build_sgemm1_k,
                   dim3(SG1_BLOCKS + N_NODES), dim3(256), args);
    }
    {
        void* args[] = {&h1, (void*)&a1s, (void*)&a1d};
        launch_pdl((const void*)rowdots_t<D_HID>, dim3(N_NODES / 8), dim3(256), args);
    }
    {
        void* args[] = {&h1};
        launch_pdl((const void*)attn_spmm_t<D_HID>, dim3(N_NODES), dim3(256), args);
    }

    // layer 2
    {
        void* args[] = {&h2};
        launch_pdl((const void*)gemm2_k,
                   dim3(D_OUT / GBN, N_NODES / GBM), dim3(256), args);
    }
    {
        void* args[] = {&h2, (void*)&a2s, (void*)&a2d};
        launch_pdl((const void*)rowdots_t<D_OUT>, dim3(N_NODES / 8), dim3(256), args);
    }
    {
        void* args[] = {&h2};
        launch_pdl((const void*)attn_spmm_t<D_OUT>, dim3(N_NODES), dim3(256), args);
    }

    // link scoring
    {
        void* args[] = {&hb};
        launch_pdl((const void*)gemm3_k,
                   dim3(D_OUT / GBN, N_NODES / GBM), dim3(256), args);
    }
    {
        void* args[] = {(void*)&pairs, (void*)&bb, &out, (void*)&P};
        launch_pdl((const void*)pairs_k, dim3((P * 32 + 255) / 256), dim3(256), args);
    }
}

// round 15
// speedup vs baseline: 1.0602x; 1.0602x over previous
#include <cuda_runtime.h>
#include <cuda_bf16.h>
#include <math.h>

// ============================================================================
// DMAModel: 2-layer weighted GAT + link scoring (sparse formulation).
// GEMMs: bf16x3 tensor cores (pre-split hi/lo), cp.async + ldmatrix.
// Attention: fused 128-thread blocks, 2-barrier softmax (wv folded into pass 2,
// 1/sum folded into epilogue), split-array gather. PDL across the whole chain.
// ============================================================================

#define N_NODES 4096
#define D_IN    256
#define D_HID   512
#define D_OUT   256
#define CAP     512

typedef unsigned short ushort_t;

// ---------------- scratch (device globals) ----------------------------------
__device__ float    g_h1 [N_NODES * D_HID];
__device__ float    g_h2 [N_NODES * D_OUT];
__device__ float    g_o2 [N_NODES * D_OUT];
__device__ float    g_hb [N_NODES * D_OUT];
__device__ float    g_src[N_NODES];
__device__ float    g_dst[N_NODES];
__device__ int      g_cols[(size_t)N_NODES * CAP];
__device__ float    g_wv  [(size_t)N_NODES * CAP];
__device__ int      g_cnt [N_NODES];
// bf16 hi/lo split operands
__device__ ushort_t g_xh [N_NODES * D_IN],  g_xl [N_NODES * D_IN];
__device__ ushort_t g_w1h[D_IN * D_HID],    g_w1l[D_IN * D_HID];
__device__ ushort_t g_w2h[D_HID * D_OUT],   g_w2l[D_HID * D_OUT];
__device__ ushort_t g_wbh[D_OUT * D_OUT],   g_wbl[D_OUT * D_OUT];
__device__ ushort_t g_o1h[N_NODES * D_HID], g_o1l[N_NODES * D_HID];
__device__ ushort_t g_o2h[N_NODES * D_OUT], g_o2l[N_NODES * D_OUT];

// ---------------- bf16 helpers ------------------------------------------------
__device__ __forceinline__ unsigned cvt2_bf16(float e0, float e1) {
    unsigned r;
    asm("cvt.rn.bf16x2.f32 %0, %1, %2;" : "=r"(r) : "f"(e1), "f"(e0));
    return r;
}
__device__ __forceinline__ void split2(float e0, float e1, unsigned& h, unsigned& l) {
    h = cvt2_bf16(e0, e1);
    const float h0 = __uint_as_float(h << 16);
    const float h1 = __uint_as_float(h & 0xffff0000u);
    l = cvt2_bf16(e0 - h0, e1 - h1);
}
__device__ __forceinline__ void ldm_x4(unsigned& r0, unsigned& r1,
                                       unsigned& r2, unsigned& r3, unsigned addr) {
    asm volatile("ldmatrix.sync.aligned.m8n8.x4.shared.b16 {%0,%1,%2,%3}, [%4];"
                 : "=r"(r0), "=r"(r1), "=r"(r2), "=r"(r3) : "r"(addr));
}
__device__ __forceinline__ void ldm_x4_t(unsigned& r0, unsigned& r1,
                                         unsigned& r2, unsigned& r3, unsigned addr) {
    asm volatile("ldmatrix.sync.aligned.m8n8.x4.trans.shared.b16 {%0,%1,%2,%3}, [%4];"
                 : "=r"(r0), "=r"(r1), "=r"(r2), "=r"(r3) : "r"(addr));
}
__device__ __forceinline__ void mma_bf16(float& c0, float& c1, float& c2, float& c3,
                                         unsigned a0, unsigned a1, unsigned a2, unsigned a3,
                                         unsigned b0, unsigned b1) {
    asm volatile(
        "mma.sync.aligned.m16n8k16.row.col.f32.bf16.bf16.f32 "
        "{%0,%1,%2,%3}, {%4,%5,%6,%7}, {%8,%9}, {%0,%1,%2,%3};"
        : "+f"(c0), "+f"(c1), "+f"(c2), "+f"(c3)
        : "r"(a0), "r"(a1), "r"(a2), "r"(a3), "r"(b0), "r"(b1));
}
__device__ __forceinline__ void cp16(void* d, const void* s) {
    unsigned da = (unsigned)__cvta_generic_to_shared(d);
    asm volatile("cp.async.ca.shared.global [%0], [%1], 16;" :: "r"(da), "l"(s));
}
__device__ __forceinline__ void cp_commit() { asm volatile("cp.async.commit_group;"); }
__device__ __forceinline__ void cp_wait1()  { asm volatile("cp.async.wait_group 1;"); }
__device__ __forceinline__ void cp_wait0()  { asm volatile("cp.async.wait_group 0;"); }

// ---------------- startup split: x, W1, W2, Wb -> bf16 hi/lo ------------------
#define XF4  (N_NODES * D_IN  / 4)
#define W1F4 (D_IN    * D_HID / 4)
#define W2F4 (D_HID   * D_OUT / 4)
#define WBF4 (D_OUT   * D_OUT / 4)
#define SPLIT_BLOCKS ((XF4 + W1F4 + W2F4 + WBF4) / 256)    // 1344

__global__ __launch_bounds__(256) void split_inputs_k(const float* __restrict__ x,
                                                      const float* __restrict__ W1,
                                                      const float* __restrict__ W2,
                                                      const float* __restrict__ Wb)
{
    const int idx = blockIdx.x * 256 + threadIdx.x;
    const float* src; ushort_t *dh, *dl; int l;
    if (idx < XF4)                     { src = x;  dh = g_xh;  dl = g_xl;  l = idx; }
    else if (idx < XF4 + W1F4)         { src = W1; dh = g_w1h; dl = g_w1l; l = idx - XF4; }
    else if (idx < XF4 + W1F4 + W2F4)  { src = W2; dh = g_w2h; dl = g_w2l; l = idx - XF4 - W1F4; }
    else                               { src = Wb; dh = g_wbh; dl = g_wbl; l = idx - XF4 - W1F4 - W2F4; }
    const float4 v = ((const float4*)src)[l];
    unsigned h0, l0, h1, l1;
    split2(v.x, v.y, h0, l0);
    split2(v.z, v.w, h1, l1);
    ((uint2*)dh)[l] = make_uint2(h0, h1);
    ((uint2*)dl)[l] = make_uint2(l0, l1);
    cudaTriggerProgrammaticLaunchCompletion();
}

// ---------------- bf16x3 tensor-core GEMM ------------------------------------
#define GBM 64
#define GBN 64
#define GBK 32
#define AS  40
#define BS  72

struct __align__(16) SmemBuf {
    ushort_t Ah[GBM][AS];
    ushort_t Al[GBM][AS];
    ushort_t Bh[GBK][BS];
    ushort_t Bl[GBK][BS];
};

__device__ __forceinline__ void gemm_issue(SmemBuf* sb,
                                           const ushort_t* __restrict__ Ahg,
                                           const ushort_t* __restrict__ Alg,
                                           const ushort_t* __restrict__ Bhg,
                                           const ushort_t* __restrict__ Blg,
                                           int N, int K, int bm, int bn, int c, int tid)
{
    const int aRow = tid >> 2, aSeg = (tid & 3) * 8;
    const size_t aOff = (size_t)(bm + aRow) * K + c * GBK + aSeg;
    cp16(&sb->Ah[aRow][aSeg], Ahg + aOff);
    cp16(&sb->Al[aRow][aSeg], Alg + aOff);
    const int bRow = tid >> 3, bSeg = (tid & 7) * 8;
    const size_t bOff = (size_t)(c * GBK + bRow) * N + bn + bSeg;
    cp16(&sb->Bh[bRow][bSeg], Bhg + bOff);
    cp16(&sb->Bl[bRow][bSeg], Blg + bOff);
    cp_commit();
}

__device__ __forceinline__ void bf16_gemm_body(const ushort_t* __restrict__ Ahg,
                                               const ushort_t* __restrict__ Alg,
                                               const ushort_t* __restrict__ Bhg,
                                               const ushort_t* __restrict__ Blg,
                                               float* __restrict__ C,
                                               int N, int K, int bm, int bn,
                                               SmemBuf* sb)
{
    const int tid  = threadIdx.x;
    const int lane = tid & 31;
    const int wid  = tid >> 5;
    const int g    = lane >> 2;
    const int tig  = lane & 3;
    const int m_off = (wid & 3) * 16;
    const int n_off = (wid >> 2) * 32;

    unsigned ah_p[2], al_p[2], bh_p[2], bl_p[2];
    #pragma unroll
    for (int b = 0; b < 2; b++) {
        ah_p[b] = (unsigned)__cvta_generic_to_shared(
            &sb[b].Ah[m_off + (lane & 15)][(lane >> 4) * 8]);
        al_p[b] = (unsigned)__cvta_generic_to_shared(
            &sb[b].Al[m_off + (lane & 15)][(lane >> 4) * 8]);
        bh_p[b] = (unsigned)__cvta_generic_to_shared(
            &sb[b].Bh[lane & 15][(lane >> 4) * 8]);
        bl_p[b] = (unsigned)__cvta_generic_to_shared(
            &sb[b].Bl[lane & 15][(lane >> 4) * 8]);
    }

    float acc[4][4];
    #pragma unroll
    for (int nt = 0; nt < 4; nt++)
        #pragma unroll
        for (int r = 0; r < 4; r++) acc[nt][r] = 0.0f;

    const int nchunks = K / GBK;
    gemm_issue(&sb[0], Ahg, Alg, Bhg, Blg, N, K, bm, bn, 0, tid);

    for (int c = 0; c < nchunks; c++) {
        if (c + 1 < nchunks) {
            gemm_issue(&sb[(c + 1) & 1], Ahg, Alg, Bhg, Blg, N, K, bm, bn, c + 1, tid);
            cp_wait1();
        } else {
            cp_wait0();
        }
        __syncthreads();

        const int b = c & 1;
        #pragma unroll
        for (int kc = 0; kc < 2; kc++) {
            unsigned ah0, ah1, ah2, ah3, al0, al1, al2, al3;
            ldm_x4(ah0, ah1, ah2, ah3, ah_p[b] + kc * 32);
            ldm_x4(al0, al1, al2, al3, al_p[b] + kc * 32);
            unsigned bh[8], bl[8];
            const unsigned brow_off = kc * (16 * BS * 2);
            ldm_x4_t(bh[0], bh[1], bh[2], bh[3], bh_p[b] + brow_off + n_off * 2);
            ldm_x4_t(bh[4], bh[5], bh[6], bh[7], bh_p[b] + brow_off + (n_off + 16) * 2);
            ldm_x4_t(bl[0], bl[1], bl[2], bl[3], bl_p[b] + brow_off + n_off * 2);
            ldm_x4_t(bl[4], bl[5], bl[6], bl[7], bl_p[b] + brow_off + (n_off + 16) * 2);

            #pragma unroll
            for (int nt = 0; nt < 4; nt++) {
                mma_bf16(acc[nt][0], acc[nt][1], acc[nt][2], acc[nt][3],
                         ah0, ah1, ah2, ah3, bh[2 * nt], bh[2 * nt + 1]);
                mma_bf16(acc[nt][0], acc[nt][1], acc[nt][2], acc[nt][3],
                         ah0, ah1, ah2, ah3, bl[2 * nt], bl[2 * nt + 1]);
                mma_bf16(acc[nt][0], acc[nt][1], acc[nt][2], acc[nt][3],
                         al0, al1, al2, al3, bh[2 * nt], bh[2 * nt + 1]);
            }
        }
        __syncthreads();
    }

    const int row0 = bm + m_off + g;
    #pragma unroll
    for (int nt = 0; nt < 4; nt++) {
        const int col = bn + n_off + nt * 8 + 2 * tig;
        *(float2*)(C + (size_t)row0 * N + col)       = make_float2(acc[nt][0], acc[nt][1]);
        *(float2*)(C + (size_t)(row0 + 8) * N + col) = make_float2(acc[nt][2], acc[nt][3]);
    }
}

// ---------------- sparse build body ------------------------------------------
__device__ __forceinline__ void build_row(const float* __restrict__ adj,
                                          const float* __restrict__ amount,
                                          const float* __restrict__ count,
                                          int i)
{
    const int tid  = threadIdx.x;
    const int lane = tid & 31, warp = tid >> 5;
    __shared__ int s_wsum[8];
    __shared__ int s_total;

    const float4* arow4 = (const float4*)(adj + (size_t)i * N_NODES);
    float4 v[4];
    #pragma unroll
    for (int t = 0; t < 4; t++) v[t] = arow4[tid * 4 + t];

    unsigned m16 = 0;
    #pragma unroll
    for (int t = 0; t < 4; t++) {
        if (v[t].x > 0.0f) m16 |= 1u << (t * 4 + 0);
        if (v[t].y > 0.0f) m16 |= 1u << (t * 4 + 1);
        if (v[t].z > 0.0f) m16 |= 1u << (t * 4 + 2);
        if (v[t].w > 0.0f) m16 |= 1u << (t * 4 + 3);
    }
    const int c = __popc(m16);

    int x = c;
    #pragma unroll
    for (int o = 1; o < 32; o <<= 1) {
        int y = __shfl_up_sync(0xffffffffu, x, o);
        if (lane >= o) x += y;
    }
    if (lane == 31) s_wsum[warp] = x;
    __syncthreads();
    if (tid == 0) {
        int acc = 0;
        #pragma unroll
        for (int w = 0; w < 8; w++) { int t = s_wsum[w]; s_wsum[w] = acc; acc += t; }
        s_total = acc;
    }
    __syncthreads();

    int pos = s_wsum[warp] + x - c;
    unsigned mm = m16;
    while (mm) {
        const int b = __ffs(mm) - 1;
        mm &= mm - 1;
        const int j = tid * 16 + b;
        if (pos < CAP) {
            g_cols[(size_t)i * CAP + pos] = j;
            g_wv  [(size_t)i * CAP + pos] =
                0.5f * (amount[(size_t)i * N_NODES + j] +
                        count [(size_t)i * N_NODES + j]);
        }
        pos++;
    }
    if (tid == 0) g_cnt[i] = min(s_total, CAP);
}

// ---------------- fat kernel: layer-1 GEMM overlapped with sparse build ------
#define SG1_BLOCKS ((D_HID / GBN) * (N_NODES / GBM))   // 512
__global__ __launch_bounds__(256) void fat_build_sgemm1_k(
    float* __restrict__ h1,
    const float* __restrict__ adj, const float* __restrict__ amount,
    const float* __restrict__ count)
{
    cudaGridDependencySynchronize();
    if (blockIdx.x < SG1_BLOCKS) {
        __shared__ SmemBuf sb[2];
        const int bn = (blockIdx.x & 7) * GBN;
        const int bm = (blockIdx.x >> 3) * GBM;
        bf16_gemm_body(g_xh, g_xl, g_w1h, g_w1l, h1, D_HID, D_IN, bm, bn, sb);
    } else {
        build_row(adj, amount, count, blockIdx.x - SG1_BLOCKS);
    }
    cudaTriggerProgrammaticLaunchCompletion();
}

__global__ __launch_bounds__(256) void gemm2_k(float* __restrict__ h2)
{
    cudaGridDependencySynchronize();
    __shared__ SmemBuf sb[2];
    bf16_gemm_body(g_o1h, g_o1l, g_w2h, g_w2l, h2, D_OUT, D_HID,
                   blockIdx.y * GBM, blockIdx.x * GBN, sb);
    cudaTriggerProgrammaticLaunchCompletion();
}
__global__ __launch_bounds__(256) void gemm3_k(float* __restrict__ hb)
{
    cudaGridDependencySynchronize();
    __shared__ SmemBuf sb[2];
    bf16_gemm_body(g_o2h, g_o2l, g_wbh, g_wbl, hb, D_OUT, D_OUT,
                   blockIdx.y * GBM, blockIdx.x * GBN, sb);
    cudaTriggerProgrammaticLaunchCompletion();
}

// ---------------- rowdots: warp-per-row, MLP=4, shuffle-only reduction -------
template<int D>
__global__ __launch_bounds__(256) void rowdots_t(const float* __restrict__ h,
                                                 const float* __restrict__ asrc,
                                                 const float* __restrict__ adst)
{
    cudaGridDependencySynchronize();
    constexpr int NF4 = D / 4;
    constexpr int PERLANE = NF4 / 32;
    const int warp = threadIdx.x >> 5;
    const int lane = threadIdx.x & 31;
    const int i = blockIdx.x * 8 + warp;

    const float4* hr = (const float4*)(h + (size_t)i * D);
    const float4* a4 = (const float4*)asrc;
    const float4* b4 = (const float4*)adst;

    float4 hv[PERLANE];
    #pragma unroll
    for (int t = 0; t < PERLANE; t++) hv[t] = hr[lane + t * 32];

    float s1 = 0.0f, s2 = 0.0f;
    #pragma unroll
    for (int t = 0; t < PERLANE; t++) {
        const float4 v = hv[t];
        const float4 a = a4[lane + t * 32];
        const float4 b = b4[lane + t * 32];
        s1 += v.x * a.x + v.y * a.y + v.z * a.z + v.w * a.w;
        s2 += v.x * b.x + v.y * b.y + v.z * b.z + v.w * b.w;
    }
    #pragma unroll
    for (int o = 16; o > 0; o >>= 1) {
        s1 += __shfl_down_sync(0xffffffffu, s1, o);
        s2 += __shfl_down_sync(0xffffffffu, s2, o);
    }
    if (lane == 0) { g_src[i] = s1; g_dst[i] = s2; }
    cudaTriggerProgrammaticLaunchCompletion();
}

// ---------------- fused sparse attention softmax + SpMM + ELU ----------------
// 128 threads/block (R13 shape). 2-barrier softmax: pass 2 folds wv into s_p;
// the 1/sum scale is applied once to acc in the epilogue.
template<int D>
__global__ __launch_bounds__(128) void attn_spmm_t(const float* __restrict__ h)
{
    cudaGridDependencySynchronize();
    constexpr int TPB = 128;
    constexpr int NF4 = D / 4;            // 128 (D=512) or 64 (D=256)
    constexpr int NGR = TPB / NF4;        // 1 or 2
    const int i = blockIdx.x;
    const int tid = threadIdx.x;
    const int lane = tid & 31;
    const int warp = tid >> 5;
    const int cnt = g_cnt[i];

    __shared__ float s_p  [CAP];
    __shared__ int   s_off[CAP];
    __shared__ float red  [8];

    // ---- pass 1: e + row max ----
    const float si = g_src[i];
    float lmax = -3.4e38f;
    for (int k = tid; k < cnt; k += TPB) {
        const int c = g_cols[(size_t)i * CAP + k];
        s_off[k] = c * D;
        float e = si + g_dst[c];
        e = (e >= 0.0f) ? e : 0.2f * e;
        s_p[k] = e;
        lmax = fmaxf(lmax, e);
    }
    #pragma unroll
    for (int o = 16; o > 0; o >>= 1)
        lmax = fmaxf(lmax, __shfl_xor_sync(0xffffffffu, lmax, o));
    if (lane == 0) red[warp] = lmax;
    __syncthreads();
    const float m = fmaxf(fmaxf(red[0], red[1]), fmaxf(red[2], red[3]));

    // ---- pass 2: exp + row sum; fold wv into s_p ----
    float lsum = 0.0f;
    for (int k = tid; k < cnt; k += TPB) {
        const float ex = __expf(s_p[k] - m);
        lsum += ex;
        s_p[k] = ex * g_wv[(size_t)i * CAP + k];
    }
    #pragma unroll
    for (int o = 16; o > 0; o >>= 1)
        lsum += __shfl_xor_sync(0xffffffffu, lsum, o);
    if (lane == 0) red[4 + warp] = lsum;
    __syncthreads();
    const float inv = (cnt > 0)
        ? (1.0f / ((red[4] + red[5]) + (red[6] + red[7]))) : 0.0f;

    // ---- gather + scale + ELU ----
    const int g  = tid / NF4;
    const int d4 = tid % NF4;
    float4 acc = make_float4(0.f, 0.f, 0.f, 0.f);
    #pragma unroll 4
    for (int k = g; k < cnt; k += NGR) {
        const float4 v = *(const float4*)(h + s_off[k] + (d4 << 2));
        const float p = s_p[k];
        acc.x += p * v.x; acc.y += p * v.y;
        acc.z += p * v.z; acc.w += p * v.w;
    }
    if (NGR > 1) {
        __shared__ float4 s_acc[TPB / 2];
        if (g > 0) s_acc[d4] = acc;
        __syncthreads();
        if (g == 0) {
            const float4 o = s_acc[d4];
            acc.x += o.x; acc.y += o.y; acc.z += o.z; acc.w += o.w;
        }
    }
    if (g == 0) {
        acc.x *= inv; acc.y *= inv; acc.z *= inv; acc.w *= inv;
        float4 r;
        r.x = (acc.x > 0.0f) ? acc.x : expm1f(acc.x);
        r.y = (acc.y > 0.0f) ? acc.y : expm1f(acc.y);
        r.z = (acc.z > 0.0f) ? acc.z : expm1f(acc.z);
        r.w = (acc.w > 0.0f) ? acc.w : expm1f(acc.w);
        const size_t off = (size_t)i * D + (d4 << 2);
        if (D == 256) *(float4*)(g_o2 + off) = r;
        unsigned h0, l0, h1, l1;
        split2(r.x, r.y, h0, l0);
        split2(r.z, r.w, h1, l1);
        ushort_t* oh = (D == 512) ? g_o1h : g_o2h;
        ushort_t* ol = (D == 512) ? g_o1l : g_o2l;
        *(uint2*)(oh + off) = make_uint2(h0, h1);
        *(uint2*)(ol + off) = make_uint2(l0, l1);
    }
    cudaTriggerProgrammaticLaunchCompletion();
}

// ---------------- pair scoring: sigmoid(H[i].h[j] + bb) ----------------------
__global__ __launch_bounds__(256) void pairs_k(const int* __restrict__ pairs,
                                               const float* __restrict__ bb,
                                               float* __restrict__ out, int P)
{
    cudaGridDependencySynchronize();
    const int wid  = (blockIdx.x * blockDim.x + threadIdx.x) >> 5;
    const int lane = threadIdx.x & 31;
    if (wid >= P) return;
    const int i = pairs[2 * wid + 0];
    const int j = pairs[2 * wid + 1];
    const float4* ra = (const float4*)(g_hb + (size_t)i * D_OUT);
    const float4* rb = (const float4*)(g_o2 + (size_t)j * D_OUT);
    float s = 0.0f;
    #pragma unroll
    for (int t = lane; t < D_OUT / 4; t += 32) {
        const float4 a = ra[t], b = rb[t];
        s += a.x * b.x + a.y * b.y + a.z * b.z + a.w * b.w;
    }
    #pragma unroll
    for (int o = 16; o > 0; o >>= 1) s += __shfl_down_sync(0xffffffffu, s, o);
    if (lane == 0) out[wid] = 1.0f / (1.0f + expf(-(s + bb[0])));
}

// ---------------- PDL launch helper ------------------------------------------
static inline void launch_pdl(const void* fn, dim3 grid, dim3 block, void** args)
{
    cudaLaunchConfig_t cfg = {};
    cfg.gridDim = grid;
    cfg.blockDim = block;
    cfg.dynamicSmemBytes = 0;
    cudaLaunchAttribute attr[1];
    attr[0].id = cudaLaunchAttributeProgrammaticStreamSerialization;
    attr[0].val.programmaticStreamSerializationAllowed = 1;
    cfg.attrs = attr;
    cfg.numAttrs = 1;
    cudaLaunchKernelExC(&cfg, fn, args);
}

// ============================================================================
extern "C" void kernel_launch(void* const* d_in, const int* in_sizes, int n_in,
                              void* d_out, int out_size)
{
    const float* x      = (const float*)d_in[0];
    const float* adj    = (const float*)d_in[1];
    const float* amount = (const float*)d_in[2];
    const float* count  = (const float*)d_in[3];
    const int*   pairs  = (const int*)  d_in[4];
    const float* W1     = (const float*)d_in[5];
    const float* a1s    = (const float*)d_in[6];
    const float* a1d    = (const float*)d_in[7];
    const float* W2     = (const float*)d_in[8];
    const float* a2s    = (const float*)d_in[9];
    const float* a2d    = (const float*)d_in[10];
    const float* Wb     = (const float*)d_in[11];
    const float* bb     = (const float*)d_in[12];
    float* out = (float*)d_out;
    const int P = in_sizes[4] / 2;

    float *h1, *h2, *hb;
    cudaGetSymbolAddress((void**)&h1, g_h1);
    cudaGetSymbolAddress((void**)&h2, g_h2);
    cudaGetSymbolAddress((void**)&hb, g_hb);

    // split inputs to bf16 hi/lo once (plain launch; first in chain)
    split_inputs_k<<<SPLIT_BLOCKS, 256>>>(x, W1, W2, Wb);

    // layer 1: GEMM (bf16x3) overlapped with sparse structure build
    {
        void* args[] = {&h1, (void*)&adj, (void*)&amount, (void*)&count};
        launch_pdl((const void*)fat_build_sgemm1_k,
                   dim3(SG1_BLOCKS + N_NODES), dim3(256), args);
    }
    {
        void* args[] = {&h1, (void*)&a1s, (void*)&a1d};
        launch_pdl((const void*)rowdots_t<D_HID>, dim3(N_NODES / 8), dim3(256), args);
    }
    {
        void* args[] = {&h1};
        launch_pdl((const void*)attn_spmm_t<D_HID>, dim3(N_NODES), dim3(128), args);
    }

    // layer 2
    {
        void* args[] = {&h2};
        launch_pdl((const void*)gemm2_k,
                   dim3(D_OUT / GBN, N_NODES / GBM), dim3(256), args);
    }
    {
        void* args[] = {&h2, (void*)&a2s, (void*)&a2d};
        launch_pdl((const void*)rowdots_t<D_OUT>, dim3(N_NODES / 8), dim3(256), args);
    }
    {
        void* args[] = {&h2};
        launch_pdl((const void*)attn_spmm_t<D_OUT>, dim3(N_NODES), dim3(128), args);
    }

    // link scoring
    {
        void* args[] = {&hb};
        launch_pdl((const void*)gemm3_k,
                   dim3(D_OUT / GBN, N_NODES / GBM), dim3(256), args);
    }
    {
        void* args[] = {(void*)&pairs, (void*)&bb, &out, (void*)&P};
        launch_pdl((const void*)pairs_k, dim3((P * 32 + 255) / 256), dim3(256), args);
    }
}

// round 16
// speedup vs baseline: 1.0658x; 1.0053x over previous
#include <cuda_runtime.h>
#include <cuda_bf16.h>
#include <math.h>

// ============================================================================
// DMAModel: 2-layer weighted GAT + link scoring (sparse formulation).
// GEMMs: bf16x3 tensor cores (pre-split hi/lo), cp.async + ldmatrix.
// Attention: fused 128-thread blocks, 3-barrier hybrid softmax (R13 form).
// PDL across the chain; fat kernel's build branch skips the dependency sync
// (it doesn't consume split outputs) so it overlaps with split_inputs.
// ============================================================================

#define N_NODES 4096
#define D_IN    256
#define D_HID   512
#define D_OUT   256
#define CAP     512

typedef unsigned short ushort_t;

// ---------------- scratch (device globals) ----------------------------------
__device__ float    g_h1 [N_NODES * D_HID];
__device__ float    g_h2 [N_NODES * D_OUT];
__device__ float    g_o2 [N_NODES * D_OUT];
__device__ float    g_hb [N_NODES * D_OUT];
__device__ float    g_src[N_NODES];
__device__ float    g_dst[N_NODES];
__device__ int      g_cols[(size_t)N_NODES * CAP];
__device__ float    g_wv  [(size_t)N_NODES * CAP];
__device__ int      g_cnt [N_NODES];
// bf16 hi/lo split operands
__device__ ushort_t g_xh [N_NODES * D_IN],  g_xl [N_NODES * D_IN];
__device__ ushort_t g_w1h[D_IN * D_HID],    g_w1l[D_IN * D_HID];
__device__ ushort_t g_w2h[D_HID * D_OUT],   g_w2l[D_HID * D_OUT];
__device__ ushort_t g_wbh[D_OUT * D_OUT],   g_wbl[D_OUT * D_OUT];
__device__ ushort_t g_o1h[N_NODES * D_HID], g_o1l[N_NODES * D_HID];
__device__ ushort_t g_o2h[N_NODES * D_OUT], g_o2l[N_NODES * D_OUT];

// ---------------- bf16 helpers ------------------------------------------------
__device__ __forceinline__ unsigned cvt2_bf16(float e0, float e1) {
    unsigned r;
    asm("cvt.rn.bf16x2.f32 %0, %1, %2;" : "=r"(r) : "f"(e1), "f"(e0));
    return r;
}
__device__ __forceinline__ void split2(float e0, float e1, unsigned& h, unsigned& l) {
    h = cvt2_bf16(e0, e1);
    const float h0 = __uint_as_float(h << 16);
    const float h1 = __uint_as_float(h & 0xffff0000u);
    l = cvt2_bf16(e0 - h0, e1 - h1);
}
__device__ __forceinline__ void ldm_x4(unsigned& r0, unsigned& r1,
                                       unsigned& r2, unsigned& r3, unsigned addr) {
    asm volatile("ldmatrix.sync.aligned.m8n8.x4.shared.b16 {%0,%1,%2,%3}, [%4];"
                 : "=r"(r0), "=r"(r1), "=r"(r2), "=r"(r3) : "r"(addr));
}
__device__ __forceinline__ void ldm_x4_t(unsigned& r0, unsigned& r1,
                                         unsigned& r2, unsigned& r3, unsigned addr) {
    asm volatile("ldmatrix.sync.aligned.m8n8.x4.trans.shared.b16 {%0,%1,%2,%3}, [%4];"
                 : "=r"(r0), "=r"(r1), "=r"(r2), "=r"(r3) : "r"(addr));
}
__device__ __forceinline__ void mma_bf16(float& c0, float& c1, float& c2, float& c3,
                                         unsigned a0, unsigned a1, unsigned a2, unsigned a3,
                                         unsigned b0, unsigned b1) {
    asm volatile(
        "mma.sync.aligned.m16n8k16.row.col.f32.bf16.bf16.f32 "
        "{%0,%1,%2,%3}, {%4,%5,%6,%7}, {%8,%9}, {%0,%1,%2,%3};"
        : "+f"(c0), "+f"(c1), "+f"(c2), "+f"(c3)
        : "r"(a0), "r"(a1), "r"(a2), "r"(a3), "r"(b0), "r"(b1));
}
__device__ __forceinline__ void cp16(void* d, const void* s) {
    unsigned da = (unsigned)__cvta_generic_to_shared(d);
    asm volatile("cp.async.ca.shared.global [%0], [%1], 16;" :: "r"(da), "l"(s));
}
__device__ __forceinline__ void cp_commit() { asm volatile("cp.async.commit_group;"); }
__device__ __forceinline__ void cp_wait1()  { asm volatile("cp.async.wait_group 1;"); }
__device__ __forceinline__ void cp_wait0()  { asm volatile("cp.async.wait_group 0;"); }

// ---------------- startup split: x, W1, W2, Wb -> bf16 hi/lo ------------------
#define XF4  (N_NODES * D_IN  / 4)
#define W1F4 (D_IN    * D_HID / 4)
#define W2F4 (D_HID   * D_OUT / 4)
#define WBF4 (D_OUT   * D_OUT / 4)
#define SPLIT_BLOCKS ((XF4 + W1F4 + W2F4 + WBF4) / 256)    // 1344

__global__ __launch_bounds__(256) void split_inputs_k(const float* __restrict__ x,
                                                      const float* __restrict__ W1,
                                                      const float* __restrict__ W2,
                                                      const float* __restrict__ Wb)
{
    const int idx = blockIdx.x * 256 + threadIdx.x;
    const float* src; ushort_t *dh, *dl; int l;
    if (idx < XF4)                     { src = x;  dh = g_xh;  dl = g_xl;  l = idx; }
    else if (idx < XF4 + W1F4)         { src = W1; dh = g_w1h; dl = g_w1l; l = idx - XF4; }
    else if (idx < XF4 + W1F4 + W2F4)  { src = W2; dh = g_w2h; dl = g_w2l; l = idx - XF4 - W1F4; }
    else                               { src = Wb; dh = g_wbh; dl = g_wbl; l = idx - XF4 - W1F4 - W2F4; }
    const float4 v = ((const float4*)src)[l];
    unsigned h0, l0, h1, l1;
    split2(v.x, v.y, h0, l0);
    split2(v.z, v.w, h1, l1);
    ((uint2*)dh)[l] = make_uint2(h0, h1);
    ((uint2*)dl)[l] = make_uint2(l0, l1);
    cudaTriggerProgrammaticLaunchCompletion();
}

// ---------------- bf16x3 tensor-core GEMM ------------------------------------
#define GBM 64
#define GBN 64
#define GBK 32
#define AS  40
#define BS  72

struct __align__(16) SmemBuf {
    ushort_t Ah[GBM][AS];
    ushort_t Al[GBM][AS];
    ushort_t Bh[GBK][BS];
    ushort_t Bl[GBK][BS];
};

__device__ __forceinline__ void gemm_issue(SmemBuf* sb,
                                           const ushort_t* __restrict__ Ahg,
                                           const ushort_t* __restrict__ Alg,
                                           const ushort_t* __restrict__ Bhg,
                                           const ushort_t* __restrict__ Blg,
                                           int N, int K, int bm, int bn, int c, int tid)
{
    const int aRow = tid >> 2, aSeg = (tid & 3) * 8;
    const size_t aOff = (size_t)(bm + aRow) * K + c * GBK + aSeg;
    cp16(&sb->Ah[aRow][aSeg], Ahg + aOff);
    cp16(&sb->Al[aRow][aSeg], Alg + aOff);
    const int bRow = tid >> 3, bSeg = (tid & 7) * 8;
    const size_t bOff = (size_t)(c * GBK + bRow) * N + bn + bSeg;
    cp16(&sb->Bh[bRow][bSeg], Bhg + bOff);
    cp16(&sb->Bl[bRow][bSeg], Blg + bOff);
    cp_commit();
}

__device__ __forceinline__ void bf16_gemm_body(const ushort_t* __restrict__ Ahg,
                                               const ushort_t* __restrict__ Alg,
                                               const ushort_t* __restrict__ Bhg,
                                               const ushort_t* __restrict__ Blg,
                                               float* __restrict__ C,
                                               int N, int K, int bm, int bn,
                                               SmemBuf* sb)
{
    const int tid  = threadIdx.x;
    const int lane = tid & 31;
    const int wid  = tid >> 5;
    const int g    = lane >> 2;
    const int tig  = lane & 3;
    const int m_off = (wid & 3) * 16;
    const int n_off = (wid >> 2) * 32;

    unsigned ah_p[2], al_p[2], bh_p[2], bl_p[2];
    #pragma unroll
    for (int b = 0; b < 2; b++) {
        ah_p[b] = (unsigned)__cvta_generic_to_shared(
            &sb[b].Ah[m_off + (lane & 15)][(lane >> 4) * 8]);
        al_p[b] = (unsigned)__cvta_generic_to_shared(
            &sb[b].Al[m_off + (lane & 15)][(lane >> 4) * 8]);
        bh_p[b] = (unsigned)__cvta_generic_to_shared(
            &sb[b].Bh[lane & 15][(lane >> 4) * 8]);
        bl_p[b] = (unsigned)__cvta_generic_to_shared(
            &sb[b].Bl[lane & 15][(lane >> 4) * 8]);
    }

    float acc[4][4];
    #pragma unroll
    for (int nt = 0; nt < 4; nt++)
        #pragma unroll
        for (int r = 0; r < 4; r++) acc[nt][r] = 0.0f;

    const int nchunks = K / GBK;
    gemm_issue(&sb[0], Ahg, Alg, Bhg, Blg, N, K, bm, bn, 0, tid);

    for (int c = 0; c < nchunks; c++) {
        if (c + 1 < nchunks) {
            gemm_issue(&sb[(c + 1) & 1], Ahg, Alg, Bhg, Blg, N, K, bm, bn, c + 1, tid);
            cp_wait1();
        } else {
            cp_wait0();
        }
        __syncthreads();

        const int b = c & 1;
        #pragma unroll
        for (int kc = 0; kc < 2; kc++) {
            unsigned ah0, ah1, ah2, ah3, al0, al1, al2, al3;
            ldm_x4(ah0, ah1, ah2, ah3, ah_p[b] + kc * 32);
            ldm_x4(al0, al1, al2, al3, al_p[b] + kc * 32);
            unsigned bh[8], bl[8];
            const unsigned brow_off = kc * (16 * BS * 2);
            ldm_x4_t(bh[0], bh[1], bh[2], bh[3], bh_p[b] + brow_off + n_off * 2);
            ldm_x4_t(bh[4], bh[5], bh[6], bh[7], bh_p[b] + brow_off + (n_off + 16) * 2);
            ldm_x4_t(bl[0], bl[1], bl[2], bl[3], bl_p[b] + brow_off + n_off * 2);
            ldm_x4_t(bl[4], bl[5], bl[6], bl[7], bl_p[b] + brow_off + (n_off + 16) * 2);

            #pragma unroll
            for (int nt = 0; nt < 4; nt++) {
                mma_bf16(acc[nt][0], acc[nt][1], acc[nt][2], acc[nt][3],
                         ah0, ah1, ah2, ah3, bh[2 * nt], bh[2 * nt + 1]);
                mma_bf16(acc[nt][0], acc[nt][1], acc[nt][2], acc[nt][3],
                         ah0, ah1, ah2, ah3, bl[2 * nt], bl[2 * nt + 1]);
                mma_bf16(acc[nt][0], acc[nt][1], acc[nt][2], acc[nt][3],
                         al0, al1, al2, al3, bh[2 * nt], bh[2 * nt + 1]);
            }
        }
        __syncthreads();
    }

    const int row0 = bm + m_off + g;
    #pragma unroll
    for (int nt = 0; nt < 4; nt++) {
        const int col = bn + n_off + nt * 8 + 2 * tig;
        *(float2*)(C + (size_t)row0 * N + col)       = make_float2(acc[nt][0], acc[nt][1]);
        *(float2*)(C + (size_t)(row0 + 8) * N + col) = make_float2(acc[nt][2], acc[nt][3]);
    }
}

// ---------------- sparse build body ------------------------------------------
__device__ __forceinline__ void build_row(const float* __restrict__ adj,
                                          const float* __restrict__ amount,
                                          const float* __restrict__ count,
                                          int i)
{
    const int tid  = threadIdx.x;
    const int lane = tid & 31, warp = tid >> 5;
    __shared__ int s_wsum[8];
    __shared__ int s_total;

    const float4* arow4 = (const float4*)(adj + (size_t)i * N_NODES);
    float4 v[4];
    #pragma unroll
    for (int t = 0; t < 4; t++) v[t] = arow4[tid * 4 + t];

    unsigned m16 = 0;
    #pragma unroll
    for (int t = 0; t < 4; t++) {
        if (v[t].x > 0.0f) m16 |= 1u << (t * 4 + 0);
        if (v[t].y > 0.0f) m16 |= 1u << (t * 4 + 1);
        if (v[t].z > 0.0f) m16 |= 1u << (t * 4 + 2);
        if (v[t].w > 0.0f) m16 |= 1u << (t * 4 + 3);
    }
    const int c = __popc(m16);

    int x = c;
    #pragma unroll
    for (int o = 1; o < 32; o <<= 1) {
        int y = __shfl_up_sync(0xffffffffu, x, o);
        if (lane >= o) x += y;
    }
    if (lane == 31) s_wsum[warp] = x;
    __syncthreads();
    if (tid == 0) {
        int acc = 0;
        #pragma unroll
        for (int w = 0; w < 8; w++) { int t = s_wsum[w]; s_wsum[w] = acc; acc += t; }
        s_total = acc;
    }
    __syncthreads();

    int pos = s_wsum[warp] + x - c;
    unsigned mm = m16;
    while (mm) {
        const int b = __ffs(mm) - 1;
        mm &= mm - 1;
        const int j = tid * 16 + b;
        if (pos < CAP) {
            g_cols[(size_t)i * CAP + pos] = j;
            g_wv  [(size_t)i * CAP + pos] =
                0.5f * (amount[(size_t)i * N_NODES + j] +
                        count [(size_t)i * N_NODES + j]);
        }
        pos++;
    }
    if (tid == 0) g_cnt[i] = min(s_total, CAP);
}

// ---------------- fat kernel: layer-1 GEMM overlapped with sparse build ------
// The build branch does NOT consume split_inputs outputs, so only GEMM blocks
// wait on the upstream grid (branch is block-uniform -> sync stays coherent).
#define SG1_BLOCKS ((D_HID / GBN) * (N_NODES / GBM))   // 512
__global__ __launch_bounds__(256) void fat_build_sgemm1_k(
    float* __restrict__ h1,
    const float* __restrict__ adj, const float* __restrict__ amount,
    const float* __restrict__ count)
{
    if (blockIdx.x < SG1_BLOCKS) {
        cudaGridDependencySynchronize();
        __shared__ SmemBuf sb[2];
        const int bn = (blockIdx.x & 7) * GBN;
        const int bm = (blockIdx.x >> 3) * GBM;
        bf16_gemm_body(g_xh, g_xl, g_w1h, g_w1l, h1, D_HID, D_IN, bm, bn, sb);
    } else {
        build_row(adj, amount, count, blockIdx.x - SG1_BLOCKS);
    }
    cudaTriggerProgrammaticLaunchCompletion();
}

__global__ __launch_bounds__(256) void gemm2_k(float* __restrict__ h2)
{
    cudaGridDependencySynchronize();
    __shared__ SmemBuf sb[2];
    bf16_gemm_body(g_o1h, g_o1l, g_w2h, g_w2l, h2, D_OUT, D_HID,
                   blockIdx.y * GBM, blockIdx.x * GBN, sb);
    cudaTriggerProgrammaticLaunchCompletion();
}
__global__ __launch_bounds__(256) void gemm3_k(float* __restrict__ hb)
{
    cudaGridDependencySynchronize();
    __shared__ SmemBuf sb[2];
    bf16_gemm_body(g_o2h, g_o2l, g_wbh, g_wbl, hb, D_OUT, D_OUT,
                   blockIdx.y * GBM, blockIdx.x * GBN, sb);
    cudaTriggerProgrammaticLaunchCompletion();
}

// ---------------- rowdots: warp-per-row, MLP=4, shuffle-only reduction -------
template<int D>
__global__ __launch_bounds__(256) void rowdots_t(const float* __restrict__ h,
                                                 const float* __restrict__ asrc,
                                                 const float* __restrict__ adst)
{
    cudaGridDependencySynchronize();
    constexpr int NF4 = D / 4;
    constexpr int PERLANE = NF4 / 32;
    const int warp = threadIdx.x >> 5;
    const int lane = threadIdx.x & 31;
    const int i = blockIdx.x * 8 + warp;

    const float4* hr = (const float4*)(h + (size_t)i * D);
    const float4* a4 = (const float4*)asrc;
    const float4* b4 = (const float4*)adst;

    float4 hv[PERLANE];
    #pragma unroll
    for (int t = 0; t < PERLANE; t++) hv[t] = hr[lane + t * 32];

    float s1 = 0.0f, s2 = 0.0f;
    #pragma unroll
    for (int t = 0; t < PERLANE; t++) {
        const float4 v = hv[t];
        const float4 a = a4[lane + t * 32];
        const float4 b = b4[lane + t * 32];
        s1 += v.x * a.x + v.y * a.y + v.z * a.z + v.w * a.w;
        s2 += v.x * b.x + v.y * b.y + v.z * b.z + v.w * b.w;
    }
    #pragma unroll
    for (int o = 16; o > 0; o >>= 1) {
        s1 += __shfl_down_sync(0xffffffffu, s1, o);
        s2 += __shfl_down_sync(0xffffffffu, s2, o);
    }
    if (lane == 0) { g_src[i] = s1; g_dst[i] = s2; }
    cudaTriggerProgrammaticLaunchCompletion();
}

// ---------------- fused sparse attention softmax + SpMM + ELU (R13 form) -----
template<int D>
__global__ __launch_bounds__(128) void attn_spmm_t(const float* __restrict__ h)
{
    cudaGridDependencySynchronize();
    constexpr int TPB = 128;
    constexpr int NF4 = D / 4;            // 128 (D=512) or 64 (D=256)
    constexpr int NGR = TPB / NF4;        // 1 or 2
    const int i = blockIdx.x;
    const int tid = threadIdx.x;
    const int lane = tid & 31;
    const int warp = tid >> 5;
    const int cnt = g_cnt[i];

    __shared__ float s_p  [CAP];
    __shared__ int   s_off[CAP];
    __shared__ float red  [8];

    // ---- pass 1: e + row max ----
    const float si = g_src[i];
    float lmax = -3.4e38f;
    for (int k = tid; k < cnt; k += TPB) {
        const int c = g_cols[(size_t)i * CAP + k];
        s_off[k] = c * D;
        float e = si + g_dst[c];
        e = (e >= 0.0f) ? e : 0.2f * e;
        s_p[k] = e;
        lmax = fmaxf(lmax, e);
    }
    #pragma unroll
    for (int o = 16; o > 0; o >>= 1)
        lmax = fmaxf(lmax, __shfl_xor_sync(0xffffffffu, lmax, o));
    if (lane == 0) red[warp] = lmax;
    __syncthreads();
    const float m = fmaxf(fmaxf(red[0], red[1]), fmaxf(red[2], red[3]));

    // ---- pass 2: exp + row sum ----
    float lsum = 0.0f;
    for (int k = tid; k < cnt; k += TPB) {
        const float ex = __expf(s_p[k] - m);
        s_p[k] = ex;
        lsum += ex;
    }
    #pragma unroll
    for (int o = 16; o > 0; o >>= 1)
        lsum += __shfl_xor_sync(0xffffffffu, lsum, o);
    if (lane == 0) red[4 + warp] = lsum;
    __syncthreads();
    const float inv = (cnt > 0)
        ? (1.0f / ((red[4] + red[5]) + (red[6] + red[7]))) : 0.0f;

    // ---- pass 3: scale by inv * wv ----
    for (int k = tid; k < cnt; k += TPB)
        s_p[k] = s_p[k] * inv * g_wv[(size_t)i * CAP + k];
    __syncthreads();

    // ---- gather + ELU ----
    const int g  = tid / NF4;
    const int d4 = tid % NF4;
    float4 acc = make_float4(0.f, 0.f, 0.f, 0.f);
    #pragma unroll 4
    for (int k = g; k < cnt; k += NGR) {
        const float4 v = *(const float4*)(h + s_off[k] + (d4 << 2));
        const float p = s_p[k];
        acc.x += p * v.x; acc.y += p * v.y;
        acc.z += p * v.z; acc.w += p * v.w;
    }
    if (NGR > 1) {
        __shared__ float4 s_acc[TPB / 2];
        if (g > 0) s_acc[d4] = acc;
        __syncthreads();
        if (g == 0) {
            const float4 o = s_acc[d4];
            acc.x += o.x; acc.y += o.y; acc.z += o.z; acc.w += o.w;
        }
    }
    if (g == 0) {
        float4 r;
        r.x = (acc.x > 0.0f) ? acc.x : expm1f(acc.x);
        r.y = (acc.y > 0.0f) ? acc.y : expm1f(acc.y);
        r.z = (acc.z > 0.0f) ? acc.z : expm1f(acc.z);
        r.w = (acc.w > 0.0f) ? acc.w : expm1f(acc.w);
        const size_t off = (size_t)i * D + (d4 << 2);
        if (D == 256) *(float4*)(g_o2 + off) = r;
        unsigned h0, l0, h1, l1;
        split2(r.x, r.y, h0, l0);
        split2(r.z, r.w, h1, l1);
        ushort_t* oh = (D == 512) ? g_o1h : g_o2h;
        ushort_t* ol = (D == 512) ? g_o1l : g_o2l;
        *(uint2*)(oh + off) = make_uint2(h0, h1);
        *(uint2*)(ol + off) = make_uint2(l0, l1);
    }
    cudaTriggerProgrammaticLaunchCompletion();
}

// ---------------- pair scoring: sigmoid(H[i].h[j] + bb) ----------------------
__global__ __launch_bounds__(256) void pairs_k(const int* __restrict__ pairs,
                                               const float* __restrict__ bb,
                                               float* __restrict__ out, int P)
{
    cudaGridDependencySynchronize();
    const int wid  = (blockIdx.x * blockDim.x + threadIdx.x) >> 5;
    const int lane = threadIdx.x & 31;
    if (wid >= P) return;
    const int i = pairs[2 * wid + 0];
    const int j = pairs[2 * wid + 1];
    const float4* ra = (const float4*)(g_hb + (size_t)i * D_OUT);
    const float4* rb = (const float4*)(g_o2 + (size_t)j * D_OUT);
    float s = 0.0f;
    #pragma unroll
    for (int t = lane; t < D_OUT / 4; t += 32) {
        const float4 a = ra[t], b = rb[t];
        s += a.x * b.x + a.y * b.y + a.z * b.z + a.w * b.w;
    }
    #pragma unroll
    for (int o = 16; o > 0; o >>= 1) s += __shfl_down_sync(0xffffffffu, s, o);
    if (lane == 0) out[wid] = 1.0f / (1.0f + __expf(-(s + bb[0])));
}

// ---------------- PDL launch helper ------------------------------------------
static inline void launch_pdl(const void* fn, dim3 grid, dim3 block, void** args)
{
    cudaLaunchConfig_t cfg = {};
    cfg.gridDim = grid;
    cfg.blockDim = block;
    cfg.dynamicSmemBytes = 0;
    cudaLaunchAttribute attr[1];
    attr[0].id = cudaLaunchAttributeProgrammaticStreamSerialization;
    attr[0].val.programmaticStreamSerializationAllowed = 1;
    cfg.attrs = attr;
    cfg.numAttrs = 1;
    cudaLaunchKernelExC(&cfg, fn, args);
}

// ============================================================================
extern "C" void kernel_launch(void* const* d_in, const int* in_sizes, int n_in,
                              void* d_out, int out_size)
{
    const float* x      = (const float*)d_in[0];
    const float* adj    = (const float*)d_in[1];
    const float* amount = (const float*)d_in[2];
    const float* count  = (const float*)d_in[3];
    const int*   pairs  = (const int*)  d_in[4];
    const float* W1     = (const float*)d_in[5];
    const float* a1s    = (const float*)d_in[6];
    const float* a1d    = (const float*)d_in[7];
    const float* W2     = (const float*)d_in[8];
    const float* a2s    = (const float*)d_in[9];
    const float* a2d    = (const float*)d_in[10];
    const float* Wb     = (const float*)d_in[11];
    const float* bb     = (const float*)d_in[12];
    float* out = (float*)d_out;
    const int P = in_sizes[4] / 2;

    float *h1, *h2, *hb;
    cudaGetSymbolAddress((void**)&h1, g_h1);
    cudaGetSymbolAddress((void**)&h2, g_h2);
    cudaGetSymbolAddress((void**)&hb, g_hb);

    // split inputs to bf16 hi/lo once (plain launch; first in chain)
    split_inputs_k<<<SPLIT_BLOCKS, 256>>>(x, W1, W2, Wb);

    // layer 1: GEMM (bf16x3) overlapped with sparse structure build
    // (build blocks start without waiting on split)
    {
        void* args[] = {&h1, (void*)&adj, (void*)&amount, (void*)&count};
        launch_pdl((const void*)fat_build_sgemm1_k,
                   dim3(SG1_BLOCKS + N_NODES), dim3(256), args);
    }
    {
        void* args[] = {&h1, (void*)&a1s, (void*)&a1d};
        launch_pdl((const void*)rowdots_t<D_HID>, dim3(N_NODES / 8), dim3(256), args);
    }
    {
        void* args[] = {&h1};
        launch_pdl((const void*)attn_spmm_t<D_HID>, dim3(N_NODES), dim3(128), args);
    }

    // layer 2
    {
        void* args[] = {&h2};
        launch_pdl((const void*)gemm2_k,
                   dim3(D_OUT / GBN, N_NODES / GBM), dim3(256), args);
    }
    {
        void* args[] = {&h2, (void*)&a2s, (void*)&a2d};
        launch_pdl((const void*)rowdots_t<D_OUT>, dim3(N_NODES / 8), dim3(256), args);
    }
    {
        void* args[] = {&h2};
        launch_pdl((const void*)attn_spmm_t<D_OUT>, dim3(N_NODES), dim3(128), args);
    }

    // link scoring
    {
        void* args[] = {&hb};
        launch_pdl((const void*)gemm3_k,
                   dim3(D_OUT / GBN, N_NODES / GBM), dim3(256), args);
    }
    {
        void* args[] = {(void*)&pairs, (void*)&bb, &out, (void*)&P};
        launch_pdl((const void*)pairs_k, dim3((P * 32 + 255) / 256), dim3(256), args);
    }
}